// round 7
// baseline (speedup 1.0000x reference)
#include <cuda_runtime.h>
#include <cuda_bf16.h>
#include <cstdint>

// ---------------------------------------------------------------------------
// Problem geometry
// ---------------------------------------------------------------------------
#define M_DIM 16384              // 4 * 4096 rows of x
#define K_DIM 4096
#define N_DIM 11008
#define W_ELEMS (N_DIM * K_DIM)  // 45088768
#define X_ELEMS (M_DIM * K_DIM)  // 67108864

// GEMM tiling (int8: BK=64 elems = 64 bytes per row slice)
#define BM 128
#define BN 128
#define BK 64
#define NUM_KITER (K_DIM / BK)     // 64
#define N_TILES (N_DIM / BN)       // 86
#define M_TILES (M_DIM / BM)       // 128
#define GROUP_M 8

#define ROW_BYTES 64                            // BK * 1 (int8)
#define ROW_PAD 80                              // 64B data + 16B pad (conflict-free)
#define A_STAGE_BYTES (BM * ROW_PAD)            // 10240
#define B_STAGE_BYTES (BN * ROW_PAD)            // 10240
#define STAGE_BYTES (A_STAGE_BYTES + B_STAGE_BYTES)
#define STAGES 3
#define SMEM_BYTES (STAGES * STAGE_BYTES)       // 61440

// ---------------------------------------------------------------------------
// Device scratch (allocation-free rule: __device__ globals)
// NOTE: host is aarch64 -> plain `char` is UNSIGNED. All quantized stores must
// use int8_t explicitly (the R2/R3 failure was (char) casts zeroing negatives).
// ---------------------------------------------------------------------------
__device__ __align__(1024) int8_t g_qw[W_ELEMS];   // ternary {-1,0,1}
__device__ __align__(1024) int8_t g_qx[X_ELEMS];   // integers [-128,127]
__device__ float g_row_scale[M_DIM];               // gamma_x[m] * gamma_w / 127
__device__ float g_partial[1024];
__device__ float g_gamma_w;

struct i8x4 { int8_t x, y, z, w; };

// ---------------------------------------------------------------------------
// PTX helpers (sm_80-class only)
// ---------------------------------------------------------------------------
#define CP_ASYNC16(smem_u32, gptr) \
    asm volatile("cp.async.cg.shared.global.L2::128B [%0], [%1], 16;" \
                 :: "r"(smem_u32), "l"(gptr) : "memory")

#define CP_COMMIT() asm volatile("cp.async.commit_group;" ::: "memory")
#define CP_WAIT1()  asm volatile("cp.async.wait_group 1;" ::: "memory")

#define LDM_X4(r, addr) \
    asm volatile("ldmatrix.sync.aligned.m8n8.x4.shared.b16 {%0,%1,%2,%3}, [%4];" \
                 : "=r"((r)[0]), "=r"((r)[1]), "=r"((r)[2]), "=r"((r)[3]) \
                 : "r"(addr))

#define MMA_S8(d, a, b0, b1) \
    asm volatile("mma.sync.aligned.m16n8k32.row.col.s32.s8.s8.s32 " \
                 "{%0,%1,%2,%3}, {%4,%5,%6,%7}, {%8,%9}, {%0,%1,%2,%3};" \
                 : "+r"((d)[0]), "+r"((d)[1]), "+r"((d)[2]), "+r"((d)[3]) \
                 : "r"((a)[0]), "r"((a)[1]), "r"((a)[2]), "r"((a)[3]), \
                   "r"(b0), "r"(b1))

// ---------------------------------------------------------------------------
// Kernel 1: per-block partial sums of |W|
// ---------------------------------------------------------------------------
__global__ void wabs_partial_kernel(const float4* __restrict__ w, int n4) {
    __shared__ float sdata[256];
    float s = 0.f;
    for (int i = blockIdx.x * blockDim.x + threadIdx.x; i < n4; i += gridDim.x * blockDim.x) {
        float4 v = w[i];
        s += fabsf(v.x) + fabsf(v.y) + fabsf(v.z) + fabsf(v.w);
    }
    sdata[threadIdx.x] = s;
    __syncthreads();
    for (int off = 128; off > 0; off >>= 1) {
        if (threadIdx.x < off) sdata[threadIdx.x] += sdata[threadIdx.x + off];
        __syncthreads();
    }
    if (threadIdx.x == 0) g_partial[blockIdx.x] = sdata[0];
}

// ---------------------------------------------------------------------------
// Kernel 2: finalize gamma_w = mean(|W|) + 1e-5 (deterministic tree)
// ---------------------------------------------------------------------------
__global__ void gamma_finalize_kernel() {
    __shared__ float sdata[256];
    int t = threadIdx.x;
    float s = g_partial[t] + g_partial[t + 256] + g_partial[t + 512] + g_partial[t + 768];
    sdata[t] = s;
    __syncthreads();
    for (int off = 128; off > 0; off >>= 1) {
        if (t < off) sdata[t] += sdata[t + off];
        __syncthreads();
    }
    if (t == 0) g_gamma_w = sdata[0] / (float)W_ELEMS + 1e-5f;
}

// ---------------------------------------------------------------------------
// Kernel 3: quantize W to ternary int8 {-1, 0, 1} (explicit int8_t casts!)
// ---------------------------------------------------------------------------
__global__ void quant_w_kernel(const float4* __restrict__ w, int n4) {
    const float g = g_gamma_w;
    i8x4* qw = (i8x4*)g_qw;
    for (int i = blockIdx.x * blockDim.x + threadIdx.x; i < n4; i += gridDim.x * blockDim.x) {
        float4 v = w[i];
        i8x4 q;
        q.x = (int8_t)fminf(fmaxf(rintf(v.x / g), -1.f), 1.f);
        q.y = (int8_t)fminf(fmaxf(rintf(v.y / g), -1.f), 1.f);
        q.z = (int8_t)fminf(fmaxf(rintf(v.z / g), -1.f), 1.f);
        q.w = (int8_t)fminf(fmaxf(rintf(v.w / g), -1.f), 1.f);
        *(int*)&qw[i] = *(int*)&q;
    }
}

// ---------------------------------------------------------------------------
// Kernel 4: per-row absmax quantize x to int8 + row scale. One block per row.
// ---------------------------------------------------------------------------
__global__ void quant_x_kernel(const float* __restrict__ x) {
    __shared__ float sdata[256];
    const int row = blockIdx.x;
    const int t = threadIdx.x;
    const float4* xr = (const float4*)(x + (size_t)row * K_DIM);

    float4 vv[4];
    float m = 0.f;
#pragma unroll
    for (int j = 0; j < 4; ++j) {
        float4 v = xr[t + j * 256];
        vv[j] = v;
        m = fmaxf(m, fmaxf(fmaxf(fabsf(v.x), fabsf(v.y)), fmaxf(fabsf(v.z), fabsf(v.w))));
    }
    sdata[t] = m;
    __syncthreads();
    for (int off = 128; off > 0; off >>= 1) {
        if (t < off) sdata[t] = fmaxf(sdata[t], sdata[t + off]);
        __syncthreads();
    }
    const float gx = sdata[0] + 1e-5f;

    i8x4* qr = (i8x4*)(g_qx + (size_t)row * K_DIM);
#pragma unroll
    for (int j = 0; j < 4; ++j) {
        float4 v = vv[j];
        i8x4 q;
        q.x = (int8_t)fminf(fmaxf(rintf((127.f * v.x) / gx), -128.f), 127.f);
        q.y = (int8_t)fminf(fmaxf(rintf((127.f * v.y) / gx), -128.f), 127.f);
        q.z = (int8_t)fminf(fmaxf(rintf((127.f * v.z) / gx), -128.f), 127.f);
        q.w = (int8_t)fminf(fmaxf(rintf((127.f * v.w) / gx), -128.f), 127.f);
        *(int*)&qr[t + j * 256] = *(int*)&q;
    }
    if (t == 0) g_row_scale[row] = gx * g_gamma_w * (1.0f / 127.0f);
}

// ---------------------------------------------------------------------------
// Kernel 5: int8 GEMM via mma.m16n8k32.s8 (hardware-validated H1 layout),
//   ldmatrix.x4 fragment loads on 64-byte rows, 3-stage cp.async pipeline,
//   single barrier per k-iter. Integer-exact; scales folded in epilogue.
//   A = g_qx [M, K] row-major, B = g_qw [N, K] row-major
//   out[m, n] = (sum_k A[m,k]*B[n,k]) * g_row_scale[m]
// 256 threads = 8 warps in 4(m) x 2(n); warp tile 32x64.
// ---------------------------------------------------------------------------
__global__ void __launch_bounds__(256, 2)
gemm_s8(const int8_t* __restrict__ A, const int8_t* __restrict__ B,
        float* __restrict__ out) {
    extern __shared__ char smem[];
    const uint32_t sb = (uint32_t)__cvta_generic_to_shared(smem);
    const int tid = threadIdx.x;
    const int wid = tid >> 5;
    const int lane = tid & 31;
    const int wm = wid >> 1;   // 0..3 (m)
    const int wn = wid & 1;    // 0..1 (n)

    // tile mapping with GROUP_M swizzle for L2 reuse
    const int per_group = GROUP_M * N_TILES;
    const int group = blockIdx.x / per_group;
    const int rem = blockIdx.x - group * per_group;
    const int m_tile = group * GROUP_M + (rem % GROUP_M);
    const int n_tile = rem / GROUP_M;

    const char* gA = (const char*)(A + (size_t)(m_tile * BM) * K_DIM);
    const char* gB = (const char*)(B + (size_t)(n_tile * BN) * K_DIM);
    const size_t KROW = (size_t)K_DIM;   // bytes per global row (int8)

    // stage loader: 512 A-chunks + 512 B-chunks of 16B, 256 threads -> 4 each
    const int lr = tid >> 2;        // row 0..63
    const int lc = tid & 3;         // 16B chunk within 64B row

#define LOAD_STAGE(kt, st) do {                                                     \
    uint32_t abase = sb + (uint32_t)(st) * STAGE_BYTES;                             \
    uint32_t bbase = abase + A_STAGE_BYTES;                                         \
    const char* ga = gA + (size_t)(kt) * ROW_BYTES;                                 \
    const char* gb = gB + (size_t)(kt) * ROW_BYTES;                                 \
    CP_ASYNC16(abase + lr * ROW_PAD + lc * 16,        ga + (size_t)lr * KROW + lc * 16);        \
    CP_ASYNC16(abase + (lr + 64) * ROW_PAD + lc * 16, ga + (size_t)(lr + 64) * KROW + lc * 16); \
    CP_ASYNC16(bbase + lr * ROW_PAD + lc * 16,        gb + (size_t)lr * KROW + lc * 16);        \
    CP_ASYNC16(bbase + (lr + 64) * ROW_PAD + lc * 16, gb + (size_t)(lr + 64) * KROW + lc * 16); \
    CP_COMMIT();                                                                    \
} while (0)

    int acc[2][8][4];
#pragma unroll
    for (int mt = 0; mt < 2; ++mt)
#pragma unroll
        for (int nt = 0; nt < 8; ++nt)
#pragma unroll
            for (int j = 0; j < 4; ++j) acc[mt][nt][j] = 0;

    // ldmatrix lane addressing: row index lane&15, 16B k-half lane>>4.
    // On 64B int8 rows this delivers the H1-validated s8 fragments:
    //   A x4 -> r0..r3 = a0..a3 (rows g/g+8, k-halves 0/16)
    //   B x4 -> r0,r1 = b0 of n-tiles 2np,2np+1 ; r2,r3 = b1
    const int lrow = lane & 15;
    const uint32_t lhalf = (uint32_t)(lane >> 4) * 16;

    const uint32_t a_row_off = (uint32_t)(wm * 32 + lrow) * ROW_PAD + lhalf;
    const uint32_t b_row_off = (uint32_t)(wn * 64 + lrow) * ROW_PAD + lhalf;

    // prologue: stages 0,1 into buffers 0,1
    LOAD_STAGE(0, 0);
    LOAD_STAGE(1, 1);

    int st_comp = 0;   // buffer holding stage kk
    int st_load = 2;   // buffer for stage kk+2

    for (int kk = 0; kk < NUM_KITER; ++kk) {
        CP_WAIT1();        // stage kk resident (<=1 newer group pending)
        __syncthreads();   // also fences reads of buffer st_load from iter kk-1

        if (kk + 2 < NUM_KITER) {
            LOAD_STAGE(kk + 2, st_load);
        } else {
            CP_COMMIT();   // keep group accounting uniform
        }

        const uint32_t ab = sb + (uint32_t)st_comp * STAGE_BYTES;
        const uint32_t bb = ab + A_STAGE_BYTES;

#pragma unroll
        for (int ks = 0; ks < 2; ++ks) {           // two k32 steps per BK=64
            const uint32_t kbyte = (uint32_t)ks * 32;   // 32 int8 = 32B

            uint32_t afr[2][4];
#pragma unroll
            for (int mt = 0; mt < 2; ++mt) {
                uint32_t addr = ab + a_row_off + (uint32_t)(mt * 16) * ROW_PAD + kbyte;
                LDM_X4(afr[mt], addr);
            }

            uint32_t bfr[4][4];
#pragma unroll
            for (int np = 0; np < 4; ++np) {       // pairs of n8 tiles
                uint32_t addr = bb + b_row_off + (uint32_t)(np * 16) * ROW_PAD + kbyte;
                LDM_X4(bfr[np], addr);
            }

#pragma unroll
            for (int mt = 0; mt < 2; ++mt)
#pragma unroll
                for (int nt = 0; nt < 8; ++nt) {
                    const int np = nt >> 1, sel = nt & 1;
                    MMA_S8(acc[mt][nt], afr[mt], bfr[np][sel], bfr[np][2 + sel]);
                }
        }

        st_comp = (st_comp == STAGES - 1) ? 0 : st_comp + 1;
        st_load = (st_load == STAGES - 1) ? 0 : st_load + 1;
    }

    // ---- epilogue: s32 (exact) -> f32 * row_scale, float2 stores ----
    const int mbase = m_tile * BM + wm * 32;
    const int nbase = n_tile * BN + wn * 64 + (lane & 3) * 2;
#pragma unroll
    for (int mt = 0; mt < 2; ++mt) {
        const int r0 = mbase + mt * 16 + (lane >> 2);
        const float s0 = g_row_scale[r0];
        const float s1 = g_row_scale[r0 + 8];
        float* o0 = out + (size_t)r0 * N_DIM + nbase;
        float* o1 = o0 + (size_t)8 * N_DIM;
#pragma unroll
        for (int nt = 0; nt < 8; ++nt) {
            float2 v0, v1;
            v0.x = (float)acc[mt][nt][0] * s0;
            v0.y = (float)acc[mt][nt][1] * s0;
            v1.x = (float)acc[mt][nt][2] * s1;
            v1.y = (float)acc[mt][nt][3] * s1;
            *(float2*)(o0 + nt * 8) = v0;
            *(float2*)(o1 + nt * 8) = v1;
        }
    }
#undef LOAD_STAGE
}

// ---------------------------------------------------------------------------
// Host launcher
// ---------------------------------------------------------------------------
extern "C" void kernel_launch(void* const* d_in, const int* in_sizes, int n_in,
                              void* d_out, int out_size) {
    const float* x = (const float*)d_in[0];
    const float* w = (const float*)d_in[1];
    if (n_in >= 2 && in_sizes[0] == W_ELEMS && in_sizes[1] == X_ELEMS) {
        const float* t = x; x = w; w = t;   // defensive: swapped metadata order
    }
    float* out = (float*)d_out;

    void* p_qw = nullptr;
    void* p_qx = nullptr;
    cudaGetSymbolAddress(&p_qw, g_qw);
    cudaGetSymbolAddress(&p_qx, g_qx);

    cudaFuncSetAttribute(gemm_s8, cudaFuncAttributeMaxDynamicSharedMemorySize, SMEM_BYTES);

    wabs_partial_kernel<<<1024, 256>>>((const float4*)w, W_ELEMS / 4);
    gamma_finalize_kernel<<<1, 256>>>();
    quant_w_kernel<<<4096, 256>>>((const float4*)w, W_ELEMS / 4);
    quant_x_kernel<<<M_DIM, 256>>>(x);

    gemm_s8<<<M_TILES * N_TILES, 256, SMEM_BYTES>>>(
        (const int8_t*)p_qx, (const int8_t*)p_qw, out);
}

// round 8
// speedup vs baseline: 2.2879x; 2.2879x over previous
#include <cuda_runtime.h>
#include <cuda_bf16.h>
#include <cstdint>

// ---------------------------------------------------------------------------
// Problem geometry
// ---------------------------------------------------------------------------
#define M_DIM 16384              // 4 * 4096 rows of x
#define K_DIM 4096
#define N_DIM 11008
#define W_ELEMS (N_DIM * K_DIM)  // 45088768
#define X_ELEMS (M_DIM * K_DIM)  // 67108864

// GEMM tiling (bf16): CTA 128x256, warp tile 64x64, BK=64
#define BM 128
#define BN 256
#define BK 64
#define NUM_KITER (K_DIM / BK)     // 64
#define N_TILES (N_DIM / BN)       // 43
#define M_TILES (M_DIM / BM)       // 128
#define GROUP_M 8

#define ROW_BYTES 128                           // BK * 2 (bf16)
#define ROW_PAD 144                             // 128B data + 16B pad (conflict-free)
#define A_STAGE_BYTES (BM * ROW_PAD)            // 18432
#define B_STAGE_BYTES (BN * ROW_PAD)            // 36864
#define STAGE_BYTES (A_STAGE_BYTES + B_STAGE_BYTES)  // 55296
#define STAGES 4
#define SMEM_BYTES (STAGES * STAGE_BYTES)       // 221184 (1 CTA/SM)

// ---------------------------------------------------------------------------
// Device scratch (allocation-free rule: __device__ globals)
// NOTE: aarch64 host -> plain `char` is unsigned; quantized values live in
// bf16 (exact for integers <= 128 and ternary), HMMA path only (legacy IMMA
// on sm_103 measured ~8x slower per instruction).
// ---------------------------------------------------------------------------
__device__ __align__(1024) __nv_bfloat16 g_qw[W_ELEMS];  // ternary {-1,0,1}
__device__ __align__(1024) __nv_bfloat16 g_qx[X_ELEMS];  // integers [-128,127]
__device__ float g_row_scale[M_DIM];                     // gamma_x[m]*gamma_w/127
__device__ float g_partial[1024];
__device__ float g_gamma_w;

// ---------------------------------------------------------------------------
// PTX helpers (sm_80-class only)
// ---------------------------------------------------------------------------
#define CP_ASYNC16(smem_u32, gptr) \
    asm volatile("cp.async.cg.shared.global.L2::128B [%0], [%1], 16;" \
                 :: "r"(smem_u32), "l"(gptr) : "memory")

#define CP_COMMIT() asm volatile("cp.async.commit_group;" ::: "memory")
#define CP_WAIT2()  asm volatile("cp.async.wait_group 2;" ::: "memory")

#define LDM_X4(r, addr) \
    asm volatile("ldmatrix.sync.aligned.m8n8.x4.shared.b16 {%0,%1,%2,%3}, [%4];" \
                 : "=r"((r)[0]), "=r"((r)[1]), "=r"((r)[2]), "=r"((r)[3]) \
                 : "r"(addr))

#define MMA_BF16(d, a, b0, b1) \
    asm volatile("mma.sync.aligned.m16n8k16.row.col.f32.bf16.bf16.f32 " \
                 "{%0,%1,%2,%3}, {%4,%5,%6,%7}, {%8,%9}, {%0,%1,%2,%3};" \
                 : "+f"((d)[0]), "+f"((d)[1]), "+f"((d)[2]), "+f"((d)[3]) \
                 : "r"((a)[0]), "r"((a)[1]), "r"((a)[2]), "r"((a)[3]), \
                   "r"(b0), "r"(b1))

// ---------------------------------------------------------------------------
// Kernel 1: per-block partial sums of |W|
// ---------------------------------------------------------------------------
__global__ void wabs_partial_kernel(const float4* __restrict__ w, int n4) {
    __shared__ float sdata[256];
    float s = 0.f;
    for (int i = blockIdx.x * blockDim.x + threadIdx.x; i < n4; i += gridDim.x * blockDim.x) {
        float4 v = w[i];
        s += fabsf(v.x) + fabsf(v.y) + fabsf(v.z) + fabsf(v.w);
    }
    sdata[threadIdx.x] = s;
    __syncthreads();
    for (int off = 128; off > 0; off >>= 1) {
        if (threadIdx.x < off) sdata[threadIdx.x] += sdata[threadIdx.x + off];
        __syncthreads();
    }
    if (threadIdx.x == 0) g_partial[blockIdx.x] = sdata[0];
}

// ---------------------------------------------------------------------------
// Kernel 2: finalize gamma_w = mean(|W|) + 1e-5 (deterministic tree)
// ---------------------------------------------------------------------------
__global__ void gamma_finalize_kernel() {
    __shared__ float sdata[256];
    int t = threadIdx.x;
    float s = g_partial[t] + g_partial[t + 256] + g_partial[t + 512] + g_partial[t + 768];
    sdata[t] = s;
    __syncthreads();
    for (int off = 128; off > 0; off >>= 1) {
        if (t < off) sdata[t] += sdata[t + off];
        __syncthreads();
    }
    if (t == 0) g_gamma_w = sdata[0] / (float)W_ELEMS + 1e-5f;
}

// ---------------------------------------------------------------------------
// Kernel 3: quantize W to ternary bf16 {-1, 0, 1} (exact in bf16)
// ---------------------------------------------------------------------------
__global__ void quant_w_kernel(const float4* __restrict__ w, int n4) {
    const float g = g_gamma_w;
    __nv_bfloat162* qw2 = (__nv_bfloat162*)g_qw;
    for (int i = blockIdx.x * blockDim.x + threadIdx.x; i < n4; i += gridDim.x * blockDim.x) {
        float4 v = w[i];
        float q0 = fminf(fmaxf(rintf(v.x / g), -1.f), 1.f);
        float q1 = fminf(fmaxf(rintf(v.y / g), -1.f), 1.f);
        float q2 = fminf(fmaxf(rintf(v.z / g), -1.f), 1.f);
        float q3 = fminf(fmaxf(rintf(v.w / g), -1.f), 1.f);
        qw2[i * 2]     = __floats2bfloat162_rn(q0, q1);
        qw2[i * 2 + 1] = __floats2bfloat162_rn(q2, q3);
    }
}

// ---------------------------------------------------------------------------
// Kernel 4: per-row absmax quantize x to integer bf16 + row scale. 1 block/row.
// ---------------------------------------------------------------------------
__global__ void quant_x_kernel(const float* __restrict__ x) {
    __shared__ float sdata[256];
    const int row = blockIdx.x;
    const int t = threadIdx.x;
    const float4* xr = (const float4*)(x + (size_t)row * K_DIM);

    float4 vv[4];
    float m = 0.f;
#pragma unroll
    for (int j = 0; j < 4; ++j) {
        float4 v = xr[t + j * 256];
        vv[j] = v;
        m = fmaxf(m, fmaxf(fmaxf(fabsf(v.x), fabsf(v.y)), fmaxf(fabsf(v.z), fabsf(v.w))));
    }
    sdata[t] = m;
    __syncthreads();
    for (int off = 128; off > 0; off >>= 1) {
        if (t < off) sdata[t] = fmaxf(sdata[t], sdata[t + off]);
        __syncthreads();
    }
    const float gx = sdata[0] + 1e-5f;

    __nv_bfloat162* qr = (__nv_bfloat162*)(g_qx + (size_t)row * K_DIM);
#pragma unroll
    for (int j = 0; j < 4; ++j) {
        float4 v = vv[j];
        float q0 = fminf(fmaxf(rintf((127.f * v.x) / gx), -128.f), 127.f);
        float q1 = fminf(fmaxf(rintf((127.f * v.y) / gx), -128.f), 127.f);
        float q2 = fminf(fmaxf(rintf((127.f * v.z) / gx), -128.f), 127.f);
        float q3 = fminf(fmaxf(rintf((127.f * v.w) / gx), -128.f), 127.f);
        int i = t + j * 256;
        qr[i * 2]     = __floats2bfloat162_rn(q0, q1);
        qr[i * 2 + 1] = __floats2bfloat162_rn(q2, q3);
    }
    if (t == 0) g_row_scale[row] = gx * g_gamma_w * (1.0f / 127.0f);
}

// ---------------------------------------------------------------------------
// Kernel 5: bf16 GEMM via mma.m16n8k16 (integer-exact).
//   CTA 128x256, 8 warps (2m x 4n), warp tile 64x64 -> 128B smem read per MMA.
//   BK=64, 4-stage cp.async pipeline (prefetch 3 ahead), 1 barrier/iter.
//   A = g_qx [M, K] row-major bf16, B = g_qw [N, K] row-major bf16
//   out[m, n] = (sum_k A[m,k]*B[n,k]) * g_row_scale[m]
// ---------------------------------------------------------------------------
__global__ void __launch_bounds__(256, 1)
gemm_bf16(const __nv_bfloat16* __restrict__ A, const __nv_bfloat16* __restrict__ B,
          float* __restrict__ out) {
    extern __shared__ char smem[];
    const uint32_t sb = (uint32_t)__cvta_generic_to_shared(smem);
    const int tid = threadIdx.x;
    const int wid = tid >> 5;
    const int lane = tid & 31;
    const int wm = wid >> 2;   // 0..1 (m)
    const int wn = wid & 3;    // 0..3 (n)

    // tile mapping with GROUP_M swizzle for L2 reuse
    const int per_group = GROUP_M * N_TILES;      // 344
    const int group = blockIdx.x / per_group;
    const int rem = blockIdx.x - group * per_group;
    const int m_tile = group * GROUP_M + (rem % GROUP_M);
    const int n_tile = rem / GROUP_M;

    const char* gA = (const char*)(A + (size_t)(m_tile * BM) * K_DIM);
    const char* gB = (const char*)(B + (size_t)(n_tile * BN) * K_DIM);
    const size_t KROW = (size_t)K_DIM * 2;   // bytes per global row

    // stage loader: (128 + 256) rows x 8 chunks of 16B = 3072 chunks, 12/thread
    const int lrw = tid >> 3;        // base row 0..31
    const int lcc = tid & 7;         // 16B chunk within 128B row

#define LOAD_STAGE(kt, st) do {                                                     \
    uint32_t abase = sb + (uint32_t)(st) * STAGE_BYTES + lcc * 16;                  \
    uint32_t bbase = abase + A_STAGE_BYTES;                                         \
    const char* ga = gA + (size_t)(kt) * ROW_BYTES + lcc * 16;                      \
    const char* gb = gB + (size_t)(kt) * ROW_BYTES + lcc * 16;                      \
    _Pragma("unroll")                                                               \
    for (int t = 0; t < 4; ++t) {                                                   \
        int row = lrw + t * 32;                                                     \
        CP_ASYNC16(abase + row * ROW_PAD, ga + (size_t)row * KROW);                 \
    }                                                                               \
    _Pragma("unroll")                                                               \
    for (int t = 0; t < 8; ++t) {                                                   \
        int row = lrw + t * 32;                                                     \
        CP_ASYNC16(bbase + row * ROW_PAD, gb + (size_t)row * KROW);                 \
    }                                                                               \
    CP_COMMIT();                                                                    \
} while (0)

    float acc[4][8][4];
#pragma unroll
    for (int mt = 0; mt < 4; ++mt)
#pragma unroll
        for (int nt = 0; nt < 8; ++nt)
#pragma unroll
            for (int j = 0; j < 4; ++j) acc[mt][nt][j] = 0.f;

    // ldmatrix lane addressing: row index lane&15, 16B k-half lane>>4
    const int lrow = lane & 15;
    const uint32_t lhalf = (uint32_t)(lane >> 4) * 16;

    const uint32_t a_row_off = (uint32_t)(wm * 64 + lrow) * ROW_PAD + lhalf;
    const uint32_t b_row_off = (uint32_t)(wn * 64 + lrow) * ROW_PAD + lhalf;

    // prologue: stages 0..2 into buffers 0..2
    LOAD_STAGE(0, 0);
    LOAD_STAGE(1, 1);
    LOAD_STAGE(2, 2);

    for (int kk = 0; kk < NUM_KITER; ++kk) {
        CP_WAIT2();        // stage kk resident (<=2 newer groups pending)
        __syncthreads();   // visibility + fences reads of buffer (kk+3)&3 from kk-1

        // prefetch stage kk+3 into buffer (kk+3)&3 (== (kk-1)&3, consumed at kk-1)
        if (kk + 3 < NUM_KITER) {
            LOAD_STAGE(kk + 3, (kk + 3) & 3);
        } else {
            CP_COMMIT();   // keep group accounting uniform
        }

        const uint32_t ab = sb + (uint32_t)(kk & 3) * STAGE_BYTES;
        const uint32_t bb = ab + A_STAGE_BYTES;

#pragma unroll
        for (int ks = 0; ks < 4; ++ks) {           // four k16 steps per BK=64
            const uint32_t kbyte = (uint32_t)ks * 32;   // 16 bf16 = 32B

            uint32_t afr[4][4];
#pragma unroll
            for (int mt = 0; mt < 4; ++mt) {
                uint32_t addr = ab + a_row_off + (uint32_t)(mt * 16) * ROW_PAD + kbyte;
                LDM_X4(afr[mt], addr);             // r0..r3 = a0..a3
            }

            uint32_t bfr[4][4];
#pragma unroll
            for (int np = 0; np < 4; ++np) {       // pairs of n8 tiles
                uint32_t addr = bb + b_row_off + (uint32_t)(np * 16) * ROW_PAD + kbyte;
                LDM_X4(bfr[np], addr);             // r0,r1 = b0; r2,r3 = b1
            }

#pragma unroll
            for (int mt = 0; mt < 4; ++mt)
#pragma unroll
                for (int nt = 0; nt < 8; ++nt) {
                    const int np = nt >> 1, sel = nt & 1;
                    MMA_BF16(acc[mt][nt], afr[mt], bfr[np][sel], bfr[np][2 + sel]);
                }
        }
    }

    // ---- epilogue: f32 (exact integer) * row_scale, float2 stores ----
    const int mbase = m_tile * BM + wm * 64;
    const int nbase = n_tile * BN + wn * 64 + (lane & 3) * 2;
#pragma unroll
    for (int mt = 0; mt < 4; ++mt) {
        const int r0 = mbase + mt * 16 + (lane >> 2);
        const float s0 = g_row_scale[r0];
        const float s1 = g_row_scale[r0 + 8];
        float* o0 = out + (size_t)r0 * N_DIM + nbase;
        float* o1 = o0 + (size_t)8 * N_DIM;
#pragma unroll
        for (int nt = 0; nt < 8; ++nt) {
            float2 v0, v1;
            v0.x = acc[mt][nt][0] * s0;
            v0.y = acc[mt][nt][1] * s0;
            v1.x = acc[mt][nt][2] * s1;
            v1.y = acc[mt][nt][3] * s1;
            *(float2*)(o0 + nt * 8) = v0;
            *(float2*)(o1 + nt * 8) = v1;
        }
    }
#undef LOAD_STAGE
}

// ---------------------------------------------------------------------------
// Host launcher
// ---------------------------------------------------------------------------
extern "C" void kernel_launch(void* const* d_in, const int* in_sizes, int n_in,
                              void* d_out, int out_size) {
    const float* x = (const float*)d_in[0];
    const float* w = (const float*)d_in[1];
    if (n_in >= 2 && in_sizes[0] == W_ELEMS && in_sizes[1] == X_ELEMS) {
        const float* t = x; x = w; w = t;   // defensive: swapped metadata order
    }
    float* out = (float*)d_out;

    void* p_qw = nullptr;
    void* p_qx = nullptr;
    cudaGetSymbolAddress(&p_qw, g_qw);
    cudaGetSymbolAddress(&p_qx, g_qx);

    cudaFuncSetAttribute(gemm_bf16, cudaFuncAttributeMaxDynamicSharedMemorySize, SMEM_BYTES);

    wabs_partial_kernel<<<1024, 256>>>((const float4*)w, W_ELEMS / 4);
    gamma_finalize_kernel<<<1, 256>>>();
    quant_w_kernel<<<4096, 256>>>((const float4*)w, W_ELEMS / 4);
    quant_x_kernel<<<M_DIM, 256>>>(x);

    gemm_bf16<<<M_TILES * N_TILES, 256, SMEM_BYTES>>>(
        (const __nv_bfloat16*)p_qx, (const __nv_bfloat16*)p_qw, out);
}

// round 9
// speedup vs baseline: 2.5199x; 1.1014x over previous
#include <cuda_runtime.h>
#include <cuda_bf16.h>
#include <cstdint>

// ---------------------------------------------------------------------------
// Problem geometry
// ---------------------------------------------------------------------------
#define M_DIM 16384              // 4 * 4096 rows of x
#define K_DIM 4096
#define N_DIM 11008
#define W_ELEMS (N_DIM * K_DIM)  // 45088768
#define X_ELEMS (M_DIM * K_DIM)  // 67108864

// GEMM tiling (bf16): CTA 128x128, warp tile 32x64, BK=64  (R6 champion config)
#define BM 128
#define BN 128
#define BK 64
#define NUM_KITER (K_DIM / BK)     // 64
#define N_TILES (N_DIM / BN)       // 86
#define M_TILES (M_DIM / BM)       // 128
#define GROUP_M 8

#define ROW_BYTES 128                           // BK * 2 (bf16)
#define ROW_PAD 144                             // 128B data + 16B pad (conflict-free)
#define A_STAGE_BYTES (BM * ROW_PAD)            // 18432
#define B_STAGE_BYTES (BN * ROW_PAD)            // 18432
#define STAGE_BYTES (A_STAGE_BYTES + B_STAGE_BYTES)
#define STAGES 3
#define SMEM_BYTES (STAGES * STAGE_BYTES)       // 110592 (2 CTAs/SM)

// ---------------------------------------------------------------------------
// Device scratch (allocation-free rule: __device__ globals)
// ---------------------------------------------------------------------------
__device__ __align__(1024) __nv_bfloat16 g_qw[W_ELEMS];  // ternary {-1,0,1}
__device__ __align__(1024) __nv_bfloat16 g_qx[X_ELEMS];  // integers [-128,127]
__device__ float g_row_scale[M_DIM];                     // gamma_x[m]*gamma_w/127
__device__ float g_partial[1024];

// ---------------------------------------------------------------------------
// PTX helpers (sm_80-class only)
// ---------------------------------------------------------------------------
#define CP_ASYNC16(smem_u32, gptr) \
    asm volatile("cp.async.cg.shared.global.L2::128B [%0], [%1], 16;" \
                 :: "r"(smem_u32), "l"(gptr) : "memory")

#define CP_COMMIT() asm volatile("cp.async.commit_group;" ::: "memory")
#define CP_WAIT1()  asm volatile("cp.async.wait_group 1;" ::: "memory")

#define LDM_X4(r, addr) \
    asm volatile("ldmatrix.sync.aligned.m8n8.x4.shared.b16 {%0,%1,%2,%3}, [%4];" \
                 : "=r"((r)[0]), "=r"((r)[1]), "=r"((r)[2]), "=r"((r)[3]) \
                 : "r"(addr))

#define MMA_BF16(d, a, b0, b1) \
    asm volatile("mma.sync.aligned.m16n8k16.row.col.f32.bf16.bf16.f32 " \
                 "{%0,%1,%2,%3}, {%4,%5,%6,%7}, {%8,%9}, {%0,%1,%2,%3};" \
                 : "+f"((d)[0]), "+f"((d)[1]), "+f"((d)[2]), "+f"((d)[3]) \
                 : "r"((a)[0]), "r"((a)[1]), "r"((a)[2]), "r"((a)[3]), \
                   "r"(b0), "r"(b1))

// ---------------------------------------------------------------------------
// In-block gamma_w reconstruction from the 1024 partials (deterministic tree,
// bit-identical to the old gamma_finalize kernel).
// Requires 256 threads and a float[256] shared buffer; call before other use.
// ---------------------------------------------------------------------------
__device__ __forceinline__ float reduce_gamma(float* sdata) {
    const int t = threadIdx.x;
    float s = g_partial[t] + g_partial[t + 256] + g_partial[t + 512] + g_partial[t + 768];
    sdata[t] = s;
    __syncthreads();
    for (int off = 128; off > 0; off >>= 1) {
        if (t < off) sdata[t] += sdata[t + off];
        __syncthreads();
    }
    float g = sdata[0] / (float)W_ELEMS + 1e-5f;
    __syncthreads();   // allow sdata reuse by caller
    return g;
}

// ---------------------------------------------------------------------------
// Kernel 0: per-block partial sums of |W|  (exactly 1024 blocks)
// ---------------------------------------------------------------------------
__global__ void wabs_partial_kernel(const float4* __restrict__ w, int n4) {
    __shared__ float sdata[256];
    float s = 0.f;
    for (int i = blockIdx.x * blockDim.x + threadIdx.x; i < n4; i += gridDim.x * blockDim.x) {
        float4 v = w[i];
        s += fabsf(v.x) + fabsf(v.y) + fabsf(v.z) + fabsf(v.w);
    }
    sdata[threadIdx.x] = s;
    __syncthreads();
    for (int off = 128; off > 0; off >>= 1) {
        if (threadIdx.x < off) sdata[threadIdx.x] += sdata[threadIdx.x + off];
        __syncthreads();
    }
    if (threadIdx.x == 0) g_partial[blockIdx.x] = sdata[0];
}

// ---------------------------------------------------------------------------
// Kernel 1: quantize W to ternary bf16 {-1, 0, 1} (gamma reduced in-block)
// ---------------------------------------------------------------------------
__global__ void quant_w_kernel(const float4* __restrict__ w, int n4) {
    __shared__ float sdata[256];
    const float g = reduce_gamma(sdata);
    __nv_bfloat162* qw2 = (__nv_bfloat162*)g_qw;
    for (int i = blockIdx.x * blockDim.x + threadIdx.x; i < n4; i += gridDim.x * blockDim.x) {
        float4 v = w[i];
        float q0 = fminf(fmaxf(rintf(v.x / g), -1.f), 1.f);
        float q1 = fminf(fmaxf(rintf(v.y / g), -1.f), 1.f);
        float q2 = fminf(fmaxf(rintf(v.z / g), -1.f), 1.f);
        float q3 = fminf(fmaxf(rintf(v.w / g), -1.f), 1.f);
        qw2[i * 2]     = __floats2bfloat162_rn(q0, q1);
        qw2[i * 2 + 1] = __floats2bfloat162_rn(q2, q3);
    }
}

// ---------------------------------------------------------------------------
// Kernel 2: per-row absmax quantize x to integer bf16 + row scale. 1 block/row.
// ---------------------------------------------------------------------------
__global__ void quant_x_kernel(const float* __restrict__ x) {
    __shared__ float sdata[256];
    const float gw = reduce_gamma(sdata);
    const int row = blockIdx.x;
    const int t = threadIdx.x;
    const float4* xr = (const float4*)(x + (size_t)row * K_DIM);

    float4 vv[4];
    float m = 0.f;
#pragma unroll
    for (int j = 0; j < 4; ++j) {
        float4 v = xr[t + j * 256];
        vv[j] = v;
        m = fmaxf(m, fmaxf(fmaxf(fabsf(v.x), fabsf(v.y)), fmaxf(fabsf(v.z), fabsf(v.w))));
    }
    sdata[t] = m;
    __syncthreads();
    for (int off = 128; off > 0; off >>= 1) {
        if (t < off) sdata[t] = fmaxf(sdata[t], sdata[t + off]);
        __syncthreads();
    }
    const float gx = sdata[0] + 1e-5f;

    __nv_bfloat162* qr = (__nv_bfloat162*)(g_qx + (size_t)row * K_DIM);
#pragma unroll
    for (int j = 0; j < 4; ++j) {
        float4 v = vv[j];
        float q0 = fminf(fmaxf(rintf((127.f * v.x) / gx), -128.f), 127.f);
        float q1 = fminf(fmaxf(rintf((127.f * v.y) / gx), -128.f), 127.f);
        float q2 = fminf(fmaxf(rintf((127.f * v.z) / gx), -128.f), 127.f);
        float q3 = fminf(fmaxf(rintf((127.f * v.w) / gx), -128.f), 127.f);
        int i = t + j * 256;
        qr[i * 2]     = __floats2bfloat162_rn(q0, q1);
        qr[i * 2 + 1] = __floats2bfloat162_rn(q2, q3);
    }
    if (t == 0) g_row_scale[row] = gx * gw * (1.0f / 127.0f);
}

// ---------------------------------------------------------------------------
// Kernel 3: bf16 GEMM via mma.m16n8k16 (integer-exact). R6 config + register
// double-buffered ldmatrix fragments.
//   CTA 128x128, 8 warps (4m x 2n), warp tile 32x64, BK=64, 3-stage cp.async,
//   1 barrier per k-iter, 2 CTAs/SM.
//   out[m, n] = (sum_k A[m,k]*B[n,k]) * g_row_scale[m]
// ---------------------------------------------------------------------------
__global__ void __launch_bounds__(256, 2)
gemm_bf16(const __nv_bfloat16* __restrict__ A, const __nv_bfloat16* __restrict__ B,
          float* __restrict__ out) {
    extern __shared__ char smem[];
    const uint32_t sb = (uint32_t)__cvta_generic_to_shared(smem);
    const int tid = threadIdx.x;
    const int wid = tid >> 5;
    const int lane = tid & 31;
    const int wm = wid >> 1;   // 0..3 (m)
    const int wn = wid & 1;    // 0..1 (n)

    // tile mapping with GROUP_M swizzle for L2 reuse
    const int per_group = GROUP_M * N_TILES;
    const int group = blockIdx.x / per_group;
    const int rem = blockIdx.x - group * per_group;
    const int m_tile = group * GROUP_M + (rem % GROUP_M);
    const int n_tile = rem / GROUP_M;

    const char* gA = (const char*)(A + (size_t)(m_tile * BM) * K_DIM);
    const char* gB = (const char*)(B + (size_t)(n_tile * BN) * K_DIM);
    const size_t KROW = (size_t)K_DIM * 2;   // bytes per global row

    // stage loader: 256 rows x 8 chunks of 16B = 2048 chunks, 8/thread
    const int lrw = tid >> 3;        // base row 0..31
    const int lcc = tid & 7;         // 16B chunk within 128B row

#define LOAD_STAGE(kt, st) do {                                                     \
    uint32_t abase = sb + (uint32_t)(st) * STAGE_BYTES + lcc * 16;                  \
    uint32_t bbase = abase + A_STAGE_BYTES;                                         \
    const char* ga = gA + (size_t)(kt) * ROW_BYTES + lcc * 16;                      \
    const char* gb = gB + (size_t)(kt) * ROW_BYTES + lcc * 16;                      \
    _Pragma("unroll")                                                               \
    for (int t = 0; t < 4; ++t) {                                                   \
        int row = lrw + t * 32;                                                     \
        CP_ASYNC16(abase + row * ROW_PAD, ga + (size_t)row * KROW);                 \
        CP_ASYNC16(bbase + row * ROW_PAD, gb + (size_t)row * KROW);                 \
    }                                                                               \
    CP_COMMIT();                                                                    \
} while (0)

    float acc[2][8][4];
#pragma unroll
    for (int mt = 0; mt < 2; ++mt)
#pragma unroll
        for (int nt = 0; nt < 8; ++nt)
#pragma unroll
            for (int j = 0; j < 4; ++j) acc[mt][nt][j] = 0.f;

    // ldmatrix lane addressing: row index lane&15, 16B k-half lane>>4
    const int lrow = lane & 15;
    const uint32_t lhalf = (uint32_t)(lane >> 4) * 16;

    const uint32_t a_row_off = (uint32_t)(wm * 32 + lrow) * ROW_PAD + lhalf;
    const uint32_t b_row_off = (uint32_t)(wn * 64 + lrow) * ROW_PAD + lhalf;

    // prologue: stages 0,1 into buffers 0,1
    LOAD_STAGE(0, 0);
    LOAD_STAGE(1, 1);

    int st_comp = 0;   // buffer holding stage kk
    int st_load = 2;   // buffer for stage kk+2

    // fragment double buffers (register-level pipeline across ks steps)
    uint32_t afr[2][2][4];   // [buf][mt][4]
    uint32_t bfr[2][4][4];   // [buf][np][4]

#define LOAD_FRAGS(base_a, base_b, ks, fb) do {                                     \
    const uint32_t kbyte = (uint32_t)(ks) * 32;                                     \
    _Pragma("unroll")                                                               \
    for (int mt = 0; mt < 2; ++mt)                                                  \
        LDM_X4(afr[fb][mt], (base_a) + a_row_off + (uint32_t)(mt * 16) * ROW_PAD + kbyte); \
    _Pragma("unroll")                                                               \
    for (int np = 0; np < 4; ++np)                                                  \
        LDM_X4(bfr[fb][np], (base_b) + b_row_off + (uint32_t)(np * 16) * ROW_PAD + kbyte); \
} while (0)

    for (int kk = 0; kk < NUM_KITER; ++kk) {
        CP_WAIT1();        // stage kk resident (<=1 newer group pending)
        __syncthreads();   // visibility + fences reads of st_load from iter kk-1

        if (kk + 2 < NUM_KITER) {
            LOAD_STAGE(kk + 2, st_load);
        } else {
            CP_COMMIT();   // keep group accounting uniform
        }

        const uint32_t ab = sb + (uint32_t)st_comp * STAGE_BYTES;
        const uint32_t bb = ab + A_STAGE_BYTES;

        LOAD_FRAGS(ab, bb, 0, 0);   // prime frag pipeline for this iter

#pragma unroll
        for (int ks = 0; ks < 4; ++ks) {           // four k16 steps per BK=64
            const int cur = ks & 1;
            if (ks < 3) LOAD_FRAGS(ab, bb, ks + 1, cur ^ 1);   // prefetch next frags
#pragma unroll
            for (int mt = 0; mt < 2; ++mt)
#pragma unroll
                for (int nt = 0; nt < 8; ++nt) {
                    const int np = nt >> 1, sel = nt & 1;
                    MMA_BF16(acc[mt][nt], afr[cur][mt], bfr[cur][np][sel], bfr[cur][np][2 + sel]);
                }
        }

        st_comp = (st_comp == STAGES - 1) ? 0 : st_comp + 1;
        st_load = (st_load == STAGES - 1) ? 0 : st_load + 1;
    }

    // ---- epilogue: f32 (exact integer) * row_scale, float2 stores ----
    const int mbase = m_tile * BM + wm * 32;
    const int nbase = n_tile * BN + wn * 64 + (lane & 3) * 2;
#pragma unroll
    for (int mt = 0; mt < 2; ++mt) {
        const int r0 = mbase + mt * 16 + (lane >> 2);
        const float s0 = g_row_scale[r0];
        const float s1 = g_row_scale[r0 + 8];
        float* o0 = out + (size_t)r0 * N_DIM + nbase;
        float* o1 = o0 + (size_t)8 * N_DIM;
#pragma unroll
        for (int nt = 0; nt < 8; ++nt) {
            float2 v0, v1;
            v0.x = acc[mt][nt][0] * s0;
            v0.y = acc[mt][nt][1] * s0;
            v1.x = acc[mt][nt][2] * s1;
            v1.y = acc[mt][nt][3] * s1;
            *(float2*)(o0 + nt * 8) = v0;
            *(float2*)(o1 + nt * 8) = v1;
        }
    }
#undef LOAD_STAGE
#undef LOAD_FRAGS
}

// ---------------------------------------------------------------------------
// Host launcher — 4 launches: wabs=0, quant_w=1, quant_x=2, gemm=3
// (gamma_finalize merged away so the profiler slot that kept landing on
//  launch index 3 now captures the GEMM.)
// ---------------------------------------------------------------------------
extern "C" void kernel_launch(void* const* d_in, const int* in_sizes, int n_in,
                              void* d_out, int out_size) {
    const float* x = (const float*)d_in[0];
    const float* w = (const float*)d_in[1];
    if (n_in >= 2 && in_sizes[0] == W_ELEMS && in_sizes[1] == X_ELEMS) {
        const float* t = x; x = w; w = t;   // defensive: swapped metadata order
    }
    float* out = (float*)d_out;

    void* p_qw = nullptr;
    void* p_qx = nullptr;
    cudaGetSymbolAddress(&p_qw, g_qw);
    cudaGetSymbolAddress(&p_qx, g_qx);

    cudaFuncSetAttribute(gemm_bf16, cudaFuncAttributeMaxDynamicSharedMemorySize, SMEM_BYTES);

    wabs_partial_kernel<<<1024, 256>>>((const float4*)w, W_ELEMS / 4);
    quant_w_kernel<<<4096, 256>>>((const float4*)w, W_ELEMS / 4);
    quant_x_kernel<<<M_DIM, 256>>>(x);

    gemm_bf16<<<M_TILES * N_TILES, 256, SMEM_BYTES>>>(
        (const __nv_bfloat16*)p_qx, (const __nv_bfloat16*)p_qw, out);
}